// round 7
// baseline (speedup 1.0000x reference)
#include <cuda_runtime.h>

#define GRID_NUM 7
#define CELLS_PER_IMG 49
#define IMG_SIZE 448.0f
#define GRID_SIZE 64.0f
#define LAMBDA_COORD 5.0f
#define LAMBDA_NOOBJ 0.1f
#define EPSF 1e-12f

#define NTHREADS 256

__device__ double g_acc;            // zero-init; reset by finalizer block
__device__ unsigned int g_count;    // zero-init; reset by finalizer block

__device__ __forceinline__ float iou_f(float bx, float by, float bw, float bh,
                                       float tx, float ty, float tw, float th,
                                       float gi, float gj) {
    float ox = gj * GRID_SIZE;
    float oy = gi * GRID_SIZE;
    float cx_p = fmaf(bx, GRID_SIZE, ox);
    float cy_p = fmaf(by, GRID_SIZE, oy);
    float w_p = bw * IMG_SIZE;
    float h_p = bh * IMG_SIZE;
    float x0p = cx_p - w_p * 0.5f, x1p = cx_p + w_p * 0.5f;
    float y0p = cy_p - h_p * 0.5f, y1p = cy_p + h_p * 0.5f;
    float cx_t = fmaf(tx, GRID_SIZE, ox);
    float cy_t = fmaf(ty, GRID_SIZE, oy);
    float w_t = tw * IMG_SIZE;
    float h_t = th * IMG_SIZE;
    float x0t = cx_t - w_t * 0.5f, x1t = cx_t + w_t * 0.5f;
    float y0t = cy_t - h_t * 0.5f;
    float y1t = cy_t + w_t * 0.5f;   // TYPO kept from reference: uses w_t
    float ux0 = fmaxf(x0p, x0t);
    float ux1 = fminf(x1p, x1t);
    float uy0 = fmaxf(y0p, y0t);
    float uy1 = fminf(y1p, y1t);
    bool valid = (ux0 < ux1) && (uy0 < uy1);
    float area_u = (ux1 - ux0) * (uy1 - uy0);
    float area_p = (x1p - x0p) * (y1p - y0p);
    float area_t = (x1t - x0t) * (y1t - y0t);
    float res = __fdividef(area_u, area_p + area_t - area_u + EPSF);
    return valid ? res : 0.0f;
}

__global__ void __launch_bounds__(NTHREADS)
yolo_loss_fused(const float* __restrict__ y_pre,
                const float* __restrict__ y_true,
                int n_cells, int n_work, float inv_b,
                float* __restrict__ out) {
    // ---- finalizer block: scheduled last (CLC order), spins until all
    //      work blocks have deposited, then writes out and resets state ----
    if (blockIdx.x == (unsigned)n_work) {
        if (threadIdx.x == 0) {
            while (atomicAdd(&g_count, 0u) < (unsigned)n_work)
                __nanosleep(200);
            __threadfence();                       // acquire
            double v = atomicAdd(&g_acc, 0.0);     // coherent L2 read
            out[0] = (float)(v * (double)inv_b);
            g_acc = 0.0;
            __threadfence();                       // order resets
            g_count = 0;                           // re-arm for next replay
        }
        return;
    }

    int tid = threadIdx.x;
    int idx = blockIdx.x * NTHREADS + tid;

    float local = 0.0f;
    if (idx < n_cells) {
        int g = idx % CELLS_PER_IMG;
        float gi = (float)(g / GRID_NUM);
        float gj = (float)(g % GRID_NUM);

        // y_pre cell: 10 floats, 40B stride -> 8B aligned -> float2 loads
        const float2* p = (const float2*)(y_pre + (size_t)idx * 10);
        float2 p01 = p[0];
        float2 p23 = p[1];
        float2 p45 = p[2];
        float2 p67 = p[3];
        float2 p89 = p[4];

        const float* t = y_true + (size_t)idx * 5;
        float t0 = t[0], t1 = t[1], t2 = t[2], t3 = t[3], t4 = t[4];

        float iou0 = iou_f(p01.x, p01.y, p23.x, p23.y, t0, t1, t2, t3, gi, gj);
        float iou1 = iou_f(p45.y, p67.x, p67.y, p89.x, t0, t1, t2, t3, gi, gj);

        bool obj = (t4 == 1.0f);
        bool c0 = iou0 > iou1;

        if (obj) {
            float conf_pre = c0 ? p45.x : p89.y;
            float conf_true = c0 ? iou0 : iou1;
            float dc = conf_pre - conf_true;
            local = dc * dc;
            float xb = c0 ? p01.x : p45.y;
            float yb = c0 ? p01.y : p67.x;
            float dx = xb - t0;
            float dy = yb - t1;
            local += LAMBDA_COORD * (dx * dx + dy * dy);
            float wb = fmaxf(c0 ? p23.x : p67.y, EPSF);
            float hb = fmaxf(c0 ? p23.y : p89.x, EPSF);
            float wt = fmaxf(t2, EPSF);
            float ht = fmaxf(t3, EPSF);
            float dw = sqrtf(wb) - sqrtf(wt);
            float dh = sqrtf(hb) - sqrtf(ht);
            local += LAMBDA_COORD * (dw * dw + dh * dh);
        } else {
            local = LAMBDA_NOOBJ * (p45.x * p45.x + p89.y * p89.y);
        }
    }

    // ---- block reduction (fp32) ----
    #pragma unroll
    for (int off = 16; off > 0; off >>= 1)
        local += __shfl_down_sync(0xFFFFFFFFu, local, off);

    __shared__ float warp_sums[NTHREADS / 32];
    int lane = tid & 31;
    int wid = tid >> 5;
    if (lane == 0) warp_sums[wid] = local;
    __syncthreads();

    if (wid == 0) {
        float v = (lane < NTHREADS / 32) ? warp_sums[lane] : 0.0f;
        #pragma unroll
        for (int off = 4; off > 0; off >>= 1)
            v += __shfl_down_sync(0xFFFFFFFFu, v, off);
        if (lane == 0) {
            // non-blocking REDs; only warp 0 lingers at the fence,
            // all other warps have already retired.
            atomicAdd(&g_acc, (double)v);
            __threadfence();                 // release: g_acc before g_count
            atomicAdd(&g_count, 1u);
        }
    }
}

extern "C" void kernel_launch(void* const* d_in, const int* in_sizes, int n_in,
                              void* d_out, int out_size) {
    const float* y_pre = (const float*)d_in[0];
    const float* y_true = (const float*)d_in[1];
    float* out = (float*)d_out;

    int n_cells = in_sizes[1] / 5;               // B * 49
    int B = n_cells / CELLS_PER_IMG;

    int n_work = (n_cells + NTHREADS - 1) / NTHREADS;
    yolo_loss_fused<<<n_work + 1, NTHREADS>>>(y_pre, y_true, n_cells, n_work,
                                              1.0f / (float)B, out);
}

// round 8
// speedup vs baseline: 1.1456x; 1.1456x over previous
#include <cuda_runtime.h>

#define GRID_NUM 7
#define CELLS_PER_IMG 49
#define IMG_SIZE 448.0f
#define GRID_SIZE 64.0f
#define LAMBDA_COORD 5.0f
#define LAMBDA_NOOBJ 0.1f
#define EPSF 1e-12f

#define NTHREADS 256

__device__ double g_acc;   // zero-init in cubin; reset by finalize each launch

__device__ __forceinline__ float iou_f(float bx, float by, float bw, float bh,
                                       float tx, float ty, float tw, float th,
                                       float gi, float gj) {
    float ox = gj * GRID_SIZE;
    float oy = gi * GRID_SIZE;
    float cx_p = fmaf(bx, GRID_SIZE, ox);
    float cy_p = fmaf(by, GRID_SIZE, oy);
    float w_p = bw * IMG_SIZE;
    float h_p = bh * IMG_SIZE;
    float x0p = cx_p - w_p * 0.5f, x1p = cx_p + w_p * 0.5f;
    float y0p = cy_p - h_p * 0.5f, y1p = cy_p + h_p * 0.5f;
    float cx_t = fmaf(tx, GRID_SIZE, ox);
    float cy_t = fmaf(ty, GRID_SIZE, oy);
    float w_t = tw * IMG_SIZE;
    float h_t = th * IMG_SIZE;
    float x0t = cx_t - w_t * 0.5f, x1t = cx_t + w_t * 0.5f;
    float y0t = cy_t - h_t * 0.5f;
    float y1t = cy_t + w_t * 0.5f;   // TYPO kept from reference: uses w_t
    float ux0 = fmaxf(x0p, x0t);
    float ux1 = fminf(x1p, x1t);
    float uy0 = fmaxf(y0p, y0t);
    float uy1 = fminf(y1p, y1t);
    bool valid = (ux0 < ux1) && (uy0 < uy1);
    float area_u = (ux1 - ux0) * (uy1 - uy0);
    float area_p = (x1p - x0p) * (y1p - y0p);
    float area_t = (x1t - x0t) * (y1t - y0t);
    float res = __fdividef(area_u, area_p + area_t - area_u + EPSF);
    return valid ? res : 0.0f;
}

__global__ void __launch_bounds__(NTHREADS)
yolo_loss_main(const float* __restrict__ y_pre,
               const float* __restrict__ y_true,
               int n_cells) {
    int tid = threadIdx.x;
    int idx = blockIdx.x * NTHREADS + tid;

    float local = 0.0f;
    if (idx < n_cells) {
        int g = idx % CELLS_PER_IMG;
        float gi = (float)(g / GRID_NUM);
        float gj = (float)(g % GRID_NUM);

        // y_pre cell: 10 floats, 40B stride -> 8B aligned -> float2 loads
        const float2* p = (const float2*)(y_pre + (size_t)idx * 10);
        float2 p01 = p[0];
        float2 p23 = p[1];
        float2 p45 = p[2];
        float2 p67 = p[3];
        float2 p89 = p[4];

        const float* t = y_true + (size_t)idx * 5;
        float t0 = t[0], t1 = t[1], t2 = t[2], t3 = t[3], t4 = t[4];

        float iou0 = iou_f(p01.x, p01.y, p23.x, p23.y, t0, t1, t2, t3, gi, gj);
        float iou1 = iou_f(p45.y, p67.x, p67.y, p89.x, t0, t1, t2, t3, gi, gj);

        bool obj = (t4 == 1.0f);
        bool c0 = iou0 > iou1;

        if (obj) {
            float conf_pre = c0 ? p45.x : p89.y;
            float conf_true = c0 ? iou0 : iou1;
            float dc = conf_pre - conf_true;
            local = dc * dc;
            float xb = c0 ? p01.x : p45.y;
            float yb = c0 ? p01.y : p67.x;
            float dx = xb - t0;
            float dy = yb - t1;
            local += LAMBDA_COORD * (dx * dx + dy * dy);
            float wb = fmaxf(c0 ? p23.x : p67.y, EPSF);
            float hb = fmaxf(c0 ? p23.y : p89.x, EPSF);
            float wt = fmaxf(t2, EPSF);
            float ht = fmaxf(t3, EPSF);
            float dw = sqrtf(wb) - sqrtf(wt);
            float dh = sqrtf(hb) - sqrtf(ht);
            local += LAMBDA_COORD * (dw * dw + dh * dh);
        } else {
            local = LAMBDA_NOOBJ * (p45.x * p45.x + p89.y * p89.y);
        }
    }

    // ---- block reduction (fp32) ----
    #pragma unroll
    for (int off = 16; off > 0; off >>= 1)
        local += __shfl_down_sync(0xFFFFFFFFu, local, off);

    __shared__ float warp_sums[NTHREADS / 32];
    int lane = tid & 31;
    int wid = tid >> 5;
    if (lane == 0) warp_sums[wid] = local;
    __syncthreads();

    if (wid == 0) {
        float v = (lane < NTHREADS / 32) ? warp_sums[lane] : 0.0f;
        #pragma unroll
        for (int off = 4; off > 0; off >>= 1)
            v += __shfl_down_sync(0xFFFFFFFFu, v, off);
        if (lane == 0)
            atomicAdd(&g_acc, (double)v);   // fire-and-forget RED.f64; no fence
    }
}

__global__ void finalize_kernel(float* __restrict__ out, float inv_b) {
    // PDL: block is resident during the main grid; park until the main grid
    // completes (completion implies full memory visibility of all REDs).
    asm volatile("griddepcontrol.wait;" ::: "memory");
    out[0] = (float)(g_acc * (double)inv_b);
    g_acc = 0.0;   // re-arm accumulator for next graph replay
}

extern "C" void kernel_launch(void* const* d_in, const int* in_sizes, int n_in,
                              void* d_out, int out_size) {
    const float* y_pre = (const float*)d_in[0];
    const float* y_true = (const float*)d_in[1];
    float* out = (float*)d_out;

    int n_cells = in_sizes[1] / 5;               // B * 49
    int B = n_cells / CELLS_PER_IMG;
    float inv_b = 1.0f / (float)B;

    int grid = (n_cells + NTHREADS - 1) / NTHREADS;
    yolo_loss_main<<<grid, NTHREADS>>>(y_pre, y_true, n_cells);

    // Programmatic dependent launch: finalize is scheduled while main runs,
    // spins in griddepcontrol.wait, wakes at main completion. Removes the
    // ~3.9us standalone-node launch overhead.
    cudaLaunchConfig_t cfg = {};
    cfg.gridDim = dim3(1, 1, 1);
    cfg.blockDim = dim3(1, 1, 1);
    cfg.dynamicSmemBytes = 0;
    cfg.stream = 0;   // same (legacy default) stream as the main launch
    cudaLaunchAttribute attrs[1];
    attrs[0].id = cudaLaunchAttributeProgrammaticStreamSerialization;
    attrs[0].val.programmaticStreamSerializationAllowed = 1;
    cfg.attrs = attrs;
    cfg.numAttrs = 1;
    cudaLaunchKernelEx(&cfg, finalize_kernel, out, inv_b);
}

// round 9
// speedup vs baseline: 1.1875x; 1.0365x over previous
#include <cuda_runtime.h>

// IoU is translation- and scale-invariant: the reference's grid offsets
// (gi/gj * 64) add to BOTH boxes and cancel in every max/min/difference,
// and scaling all coordinates by 1/64 leaves the area ratio unchanged
// (EPS=1e-12 is negligible vs areas in either unit system). So we compute
// in grid-relative units: center = b[0..1], half-width = 3.5*b[2..3]
// (since w_pixels/2 = b*448/2 = b*224 = (b*3.5)*64).

#define GRID_NUM 7
#define CELLS_PER_IMG 49
#define LAMBDA_COORD 5.0f
#define LAMBDA_NOOBJ 0.1f
#define EPSF 1e-12f

#define NTHREADS 256

__device__ double g_acc;   // zero-init in cubin; reset by finalize each launch

__device__ __forceinline__ float iou_f(float bx, float by, float bw, float bh,
                                       float tx, float ty, float tw, float th) {
    float x0p = fmaf(-3.5f, bw, bx), x1p = fmaf(3.5f, bw, bx);
    float y0p = fmaf(-3.5f, bh, by), y1p = fmaf(3.5f, bh, by);
    float x0t = fmaf(-3.5f, tw, tx), x1t = fmaf(3.5f, tw, tx);
    float y0t = fmaf(-3.5f, th, ty);
    float y1t = fmaf(3.5f, tw, ty);   // TYPO kept from reference: uses w_t
    float ux0 = fmaxf(x0p, x0t);
    float ux1 = fminf(x1p, x1t);
    float uy0 = fmaxf(y0p, y0t);
    float uy1 = fminf(y1p, y1t);
    bool valid = (ux0 < ux1) && (uy0 < uy1);
    float area_u = (ux1 - ux0) * (uy1 - uy0);
    float area_p = (49.0f * bw) * bh;                 // (7bw)*(7bh)
    float area_t = (7.0f * tw) * (y1t - y0t);         // (x1t-x0t)*(y1t-y0t)
    float res = __fdividef(area_u, area_p + area_t - area_u + EPSF);
    return valid ? res : 0.0f;
}

__global__ void __launch_bounds__(NTHREADS)
yolo_loss_main(const float* __restrict__ y_pre,
               const float* __restrict__ y_true,
               int n_cells) {
    int tid = threadIdx.x;
    int idx = blockIdx.x * NTHREADS + tid;

    float local = 0.0f;
    if (idx < n_cells) {
        // y_pre cell: 10 floats, 40B stride -> 8B aligned -> float2 loads
        const float2* p = (const float2*)(y_pre + (size_t)idx * 10);
        float2 p01 = p[0];
        float2 p23 = p[1];
        float2 p45 = p[2];
        float2 p67 = p[3];
        float2 p89 = p[4];

        const float* t = y_true + (size_t)idx * 5;
        float t0 = t[0], t1 = t[1], t2 = t[2], t3 = t[3], t4 = t[4];

        float iou0 = iou_f(p01.x, p01.y, p23.x, p23.y, t0, t1, t2, t3);
        float iou1 = iou_f(p45.y, p67.x, p67.y, p89.x, t0, t1, t2, t3);

        bool obj = (t4 == 1.0f);
        bool c0 = iou0 > iou1;

        if (obj) {
            float conf_pre = c0 ? p45.x : p89.y;
            float conf_true = c0 ? iou0 : iou1;
            float dc = conf_pre - conf_true;
            local = dc * dc;
            float xb = c0 ? p01.x : p45.y;
            float yb = c0 ? p01.y : p67.x;
            float dx = xb - t0;
            float dy = yb - t1;
            local += LAMBDA_COORD * (dx * dx + dy * dy);
            float wb = fmaxf(c0 ? p23.x : p67.y, EPSF);
            float hb = fmaxf(c0 ? p23.y : p89.x, EPSF);
            float wt = fmaxf(t2, EPSF);
            float ht = fmaxf(t3, EPSF);
            float dw = sqrtf(wb) - sqrtf(wt);
            float dh = sqrtf(hb) - sqrtf(ht);
            local += LAMBDA_COORD * (dw * dw + dh * dh);
        } else {
            local = LAMBDA_NOOBJ * (p45.x * p45.x + p89.y * p89.y);
        }
    }

    // ---- block reduction (fp32) ----
    #pragma unroll
    for (int off = 16; off > 0; off >>= 1)
        local += __shfl_down_sync(0xFFFFFFFFu, local, off);

    __shared__ float warp_sums[NTHREADS / 32];
    int lane = tid & 31;
    int wid = tid >> 5;
    if (lane == 0) warp_sums[wid] = local;
    __syncthreads();

    if (wid == 0) {
        float v = (lane < NTHREADS / 32) ? warp_sums[lane] : 0.0f;
        #pragma unroll
        for (int off = 4; off > 0; off >>= 1)
            v += __shfl_down_sync(0xFFFFFFFFu, v, off);
        if (lane == 0)
            atomicAdd(&g_acc, (double)v);   // fire-and-forget RED.f64; no fence
    }
}

__global__ void finalize_kernel(float* __restrict__ out, float inv_b) {
    // PDL: resident during the main grid; parks until main completes
    // (completion implies visibility of all REDs).
    asm volatile("griddepcontrol.wait;" ::: "memory");
    out[0] = (float)(g_acc * (double)inv_b);
    g_acc = 0.0;   // re-arm accumulator for next graph replay
}

extern "C" void kernel_launch(void* const* d_in, const int* in_sizes, int n_in,
                              void* d_out, int out_size) {
    const float* y_pre = (const float*)d_in[0];
    const float* y_true = (const float*)d_in[1];
    float* out = (float*)d_out;

    int n_cells = in_sizes[1] / 5;               // B * 49
    int B = n_cells / CELLS_PER_IMG;
    float inv_b = 1.0f / (float)B;

    int grid = (n_cells + NTHREADS - 1) / NTHREADS;
    yolo_loss_main<<<grid, NTHREADS>>>(y_pre, y_true, n_cells);

    // Programmatic dependent launch for the epilogue node.
    cudaLaunchConfig_t cfg = {};
    cfg.gridDim = dim3(1, 1, 1);
    cfg.blockDim = dim3(1, 1, 1);
    cfg.dynamicSmemBytes = 0;
    cfg.stream = 0;
    cudaLaunchAttribute attrs[1];
    attrs[0].id = cudaLaunchAttributeProgrammaticStreamSerialization;
    attrs[0].val.programmaticStreamSerializationAllowed = 1;
    cfg.attrs = attrs;
    cfg.numAttrs = 1;
    cudaLaunchKernelEx(&cfg, finalize_kernel, out, inv_b);
}